// round 11
// baseline (speedup 1.0000x reference)
#include <cuda_runtime.h>
#include <cuda_bf16.h>
#include <cstdint>
#include <math.h>

// Problem constants
#define HH 96
#define WW 96
#define BB 4
#define CIN 64
#define HW (HH*WW)

// ---------------- scratch (no allocations allowed) ----------------
__device__ float g_om[(size_t)BB * 216 * HW];        // offset-conv output
__device__ float g_fea[(size_t)BB * 64 * HW];        // activated dcn output
__device__ uint2 g_fAH[36 * 27 * 32];                // offset-conv B frags hi [chunk][ntG][lane]
__device__ uint2 g_fAL[36 * 27 * 32];                // lo
__device__ uint2 g_fBH[36 * 8 * 32];                 // conv1 B frags hi
__device__ uint2 g_fBL[36 * 8 * 32];                 // lo
__device__ uint2 g_fDH[36 * 8 * 32];                 // w_dcn B frags hi
__device__ uint2 g_fDL[36 * 8 * 32];                 // lo

// ---------------- warp MMA: m16n8k16 row.col f32.bf16.bf16.f32 ----------------
__device__ __forceinline__ void mma16816(float* d, const uint32_t* a, const uint32_t* b) {
    asm volatile(
        "mma.sync.aligned.m16n8k16.row.col.f32.bf16.bf16.f32 "
        "{%0,%1,%2,%3}, {%4,%5,%6,%7}, {%8,%9}, {%0,%1,%2,%3};"
        : "+f"(d[0]), "+f"(d[1]), "+f"(d[2]), "+f"(d[3])
        : "r"(a[0]), "r"(a[1]), "r"(a[2]), "r"(a[3]), "r"(b[0]), "r"(b[1]));
}

__device__ __forceinline__ uint32_t pack_bf16x2(float a, float b) {
    __nv_bfloat16 ha = __float2bfloat16(a);
    __nv_bfloat16 hb = __float2bfloat16(b);
    return ((uint32_t)__bfloat16_as_ushort(hb) << 16) | (uint32_t)__bfloat16_as_ushort(ha);
}

// =================================================================
// Conv weight prep: fp32 w[Cout][64ci][9tap] -> MMA B fragments, hi/lo.
// chunk = tap*4 + kc. Lane(qr,qc), row o=ntG*8+qr:
// word0 = (ci0+2qc, +1), word1 = (ci0+8+2qc, +1).
// =================================================================
__global__ void prep_conv_frag(const float* __restrict__ w,
                               uint2* __restrict__ fh, uint2* __restrict__ fl,
                               int Cout)
{
    int NTOT = Cout >> 3;
    int total = 36 * NTOT * 32;
    int i = blockIdx.x * 256 + threadIdx.x;
    if (i >= total) return;
    int lane = i & 31;
    int ntG  = (i >> 5) % NTOT;
    int chunk = i / (NTOT * 32);
    int tap = chunk >> 2;
    int ci0 = (chunk & 3) * 16;
    int qr = lane >> 2, qc = lane & 3;
    int o = ntG * 8 + qr;
    uint32_t wh[2], wl[2];
#pragma unroll
    for (int half = 0; half < 2; half++) {
        int ci = ci0 + half * 8 + qc * 2;
        float wa = w[(size_t)(o * 64 + ci) * 9 + tap];
        float wb = w[(size_t)(o * 64 + ci + 1) * 9 + tap];
        float ha = __bfloat162float(__float2bfloat16(wa));
        float hb = __bfloat162float(__float2bfloat16(wb));
        wh[half] = pack_bf16x2(ha, hb);
        wl[half] = pack_bf16x2(wa - ha, wb - hb);
    }
    fh[i] = make_uint2(wh[0], wh[1]);
    fl[i] = make_uint2(wl[0], wl[1]);
}

// =================================================================
// DCN einsum weight prep: w_dcn[64o][64gc][9k] -> per-chunk B frags.
// =================================================================
__global__ void prep_wd_frag(const float* __restrict__ wdcn,
                             uint2* __restrict__ fh, uint2* __restrict__ fl)
{
    int i = blockIdx.x * 256 + threadIdx.x;
    if (i >= 36 * 8 * 32) return;
    int lane = i & 31;
    int nt = (i >> 5) & 7;
    int chunk = i >> 8;
    int qr = lane >> 2, qc = lane & 3;
    int o = nt * 8 + qr;
    uint32_t wh[2], wl[2];
#pragma unroll
    for (int half = 0; half < 2; half++) {
        int gk = chunk * 2 + half;
        int g = gk / 9, kt = gk - 9 * g;
        int c = qc * 2;
        float wa = wdcn[(size_t)(o * 64 + g * 8 + c) * 9 + kt];
        float wb = wdcn[(size_t)(o * 64 + g * 8 + c + 1) * 9 + kt];
        float ha = __bfloat162float(__float2bfloat16(wa));
        float hb = __bfloat162float(__float2bfloat16(wb));
        wh[half] = pack_bf16x2(ha, hb);
        wl[half] = pack_bf16x2(wa - ha, wb - hb);
    }
    fh[i] = make_uint2(wh[0], wh[1]);
    fl[i] = make_uint2(wl[0], wl[1]);
}

// =================================================================
// 3x3 conv (pad 1, Cin=64) via mma.sync, 256 threads / 8 warps.
// M=128 px (8 rows x 16 cols); warp wp owns pixel row wp (one m16 tile:
// A-row r = pixel x=r for r<8, x=r-8+8 ... lane qr -> x=qr & x=qr+8).
// N handled in NPASS passes of NT*8 channels; patch staged ONCE.
// =================================================================
constexpr int PS = 72;
constexpr int PATCH_BYTES = 180 * PS * 2;   // 25920

template<int NT, int NPASS, bool RESID>
__global__ __launch_bounds__(256) void conv_mma(
    const float* __restrict__ in,
    const uint2* __restrict__ fragH, const uint2* __restrict__ fragL,
    const float* __restrict__ bias, const float* __restrict__ resid,
    float* __restrict__ out, int Cout)
{
    extern __shared__ __align__(16) char smem[];
    __nv_bfloat16* phi = (__nv_bfloat16*)smem;
    __nv_bfloat16* plo = (__nv_bfloat16*)(smem + PATCH_BYTES);

    const int tid  = threadIdx.x;
    const int wp   = tid >> 5;          // 0..7 = pixel row
    const int lane = tid & 31;
    const int qr   = lane >> 2;
    const int qc   = lane & 3;

    const int wx0 = blockIdx.x * 16;
    const int hy0 = blockIdx.y * 8;
    const int b   = blockIdx.z;
    const int NTOT = Cout >> 3;

    const float* inb = in + (size_t)b * CIN * HW;
    for (int e = tid; e < 180 * 64; e += 256) {
        int x  = e % 18;
        int y  = (e / 18) % 10;
        int ci = e / 180;
        int gy = hy0 + y - 1;
        int gx = wx0 + x - 1;
        float v = 0.f;
        if ((unsigned)gy < HH && (unsigned)gx < WW)
            v = inb[ci * HW + gy * WW + gx];
        __nv_bfloat16 h = __float2bfloat16(v);
        __nv_bfloat16 l = __float2bfloat16(v - __bfloat162float(h));
        int d = (y * 18 + x) * PS + ci;
        phi[d] = h;
        plo[d] = l;
    }
    __syncthreads();

#pragma unroll 1
    for (int pass = 0; pass < NPASS; pass++) {
        const int co0 = pass * NT * 8;

        float acc[NT][4];
#pragma unroll
        for (int nt = 0; nt < NT; nt++)
#pragma unroll
            for (int j = 0; j < 4; j++) acc[nt][j] = 0.f;

#pragma unroll 1
        for (int tap = 0; tap < 9; tap++) {
            const int ky = tap / 3, kx = tap % 3;
#pragma unroll
            for (int kc = 0; kc < 4; kc++) {
                const int ci0 = kc * 16;
                // A fragments: pixel (y=wp, x=qr) and (y=wp, x=qr+8)
                uint32_t ah[4], al[4];
                {
                    int base = ((wp + ky) * 18 + qr + kx) * PS + ci0 + qc * 2;
                    const uint32_t* ph = (const uint32_t*)phi;
                    const uint32_t* pl = (const uint32_t*)plo;
                    int i0 = base >> 1;
                    int i1 = (base + 8 * PS) >> 1;   // x + 8
                    ah[0] = ph[i0];
                    ah[1] = ph[i1];
                    ah[2] = ph[i0 + 4];
                    ah[3] = ph[i1 + 4];
                    al[0] = pl[i0];
                    al[1] = pl[i1];
                    al[2] = pl[i0 + 4];
                    al[3] = pl[i1 + 4];
                }
                const int chunk = tap * 4 + kc;
                const uint2* fh = fragH + ((size_t)chunk * NTOT + (co0 >> 3)) * 32 + lane;
                const uint2* fl = fragL + ((size_t)chunk * NTOT + (co0 >> 3)) * 32 + lane;
#pragma unroll
                for (int nt = 0; nt < NT; nt++) {
                    uint2 bh2 = __ldg(fh + nt * 32);
                    uint2 bl2 = __ldg(fl + nt * 32);
                    uint32_t bh[2] = {bh2.x, bh2.y};
                    uint32_t bl[2] = {bl2.x, bl2.y};
                    mma16816(acc[nt], ah, bh);
                    mma16816(acc[nt], ah, bl);
                    mma16816(acc[nt], al, bh);
                }
            }
        }

        // epilogue for this pass
        int gy = hy0 + wp;
        int gx = wx0 + qr;
#pragma unroll
        for (int nt = 0; nt < NT; nt++) {
            int o = co0 + nt * 8 + qc * 2;
            float b0 = bias[o], b1 = bias[o + 1];
            size_t i00 = ((size_t)(b * Cout + o) * HH + gy) * WW + gx;
            size_t i01 = i00 + HW;
            float v0 = acc[nt][0] + b0;
            float v1 = acc[nt][1] + b1;
            float v2 = acc[nt][2] + b0;
            float v3 = acc[nt][3] + b1;
            if (RESID) {
                v0 += resid[i00];     v1 += resid[i01];
                v2 += resid[i00 + 8]; v3 += resid[i01 + 8];
            }
            out[i00] = v0;
            out[i01] = v1;
            out[i00 + 8] = v2;
            out[i01 + 8] = v3;
        }
    }
}

// =================================================================
// Deformable sampling + grouped einsum via mma.sync, fused bias+leaky.
// (unchanged from R9: warp-private A staging, __syncwarp only)
// =================================================================
__global__ __launch_bounds__(128) void deform_mma_k(
    const float* __restrict__ x, const float* __restrict__ om,
    const uint2* __restrict__ fragH, const uint2* __restrict__ fragL,
    const float* __restrict__ bdcn, float* __restrict__ fea)
{
    __shared__ uint32_t sAh[128 * 9];
    __shared__ uint32_t sAl[128 * 9];

    const int tid  = threadIdx.x;
    const int wp   = tid >> 5;
    const int lane = tid & 31;
    const int qr   = lane >> 2;
    const int qc   = lane & 3;
    const int px   = tid & 15;
    const int py   = tid >> 4;

    const int wx0 = blockIdx.x * 16;
    const int hy0 = blockIdx.y * 8;
    const int b   = blockIdx.z;
    const int w0  = wx0 + px;
    const int h0  = hy0 + py;
    const int pidx = h0 * WW + w0;

    const float* omb = om + (size_t)b * 216 * HW;
    const float* xb  = x  + (size_t)b * 64  * HW;

    float acc[2][8][4];
#pragma unroll
    for (int mt = 0; mt < 2; mt++)
#pragma unroll
        for (int nt = 0; nt < 8; nt++)
#pragma unroll
            for (int j = 0; j < 4; j++) acc[mt][nt][j] = 0.f;

    int g = 0, kt = 0;

#pragma unroll 1
    for (int chunk = 0; chunk < 36; chunk++) {
#pragma unroll
        for (int half = 0; half < 2; half++) {
            const int gk = chunk * 2 + half;
            float oy = __ldg(&omb[(size_t)gk * HW + pidx]);
            float ox = __ldg(&omb[(size_t)(72 + gk) * HW + pidx]);
            float ml = __ldg(&omb[(size_t)(144 + gk) * HW + pidx]);
            float m  = 1.f / (1.f + __expf(-ml));

            float pyf = (float)(h0 + kt / 3 - 1) + oy;
            float pxf = (float)(w0 + kt % 3 - 1) + ox;
            float y0f = floorf(pyf), x0f = floorf(pxf);
            float fy = pyf - y0f, fx = pxf - x0f;
            int y0 = (int)y0f, x0 = (int)x0f;
            int y1 = y0 + 1,  x1 = x0 + 1;

            float vy0 = (y0 >= 0 && y0 < HH) ? 1.f : 0.f;
            float vy1 = (y1 >= 0 && y1 < HH) ? 1.f : 0.f;
            float vx0 = (x0 >= 0 && x0 < WW) ? 1.f : 0.f;
            float vx1 = (x1 >= 0 && x1 < WW) ? 1.f : 0.f;
            int yc0 = min(max(y0, 0), HH - 1);
            int yc1 = min(max(y1, 0), HH - 1);
            int xc0 = min(max(x0, 0), WW - 1);
            int xc1 = min(max(x1, 0), WW - 1);

            float w00 = (1.f - fy) * (1.f - fx) * vy0 * vx0 * m;
            float w01 = (1.f - fy) * fx        * vy0 * vx1 * m;
            float w10 = fy        * (1.f - fx) * vy1 * vx0 * m;
            float w11 = fy        * fx         * vy1 * vx1 * m;

            int i00 = yc0 * WW + xc0;
            int i01 = yc0 * WW + xc1;
            int i10 = yc1 * WW + xc0;
            int i11 = yc1 * WW + xc1;

            const float* xg = xb + g * 8 * HW;
#pragma unroll
            for (int c = 0; c < 8; c += 2) {
                const float* xc0p = xg + c * HW;
                const float* xc1p = xg + (c + 1) * HW;
                float v0 = w00 * __ldg(xc0p + i00) + w01 * __ldg(xc0p + i01)
                         + w10 * __ldg(xc0p + i10) + w11 * __ldg(xc0p + i11);
                float v1 = w00 * __ldg(xc1p + i00) + w01 * __ldg(xc1p + i01)
                         + w10 * __ldg(xc1p + i10) + w11 * __ldg(xc1p + i11);
                float h0v = __bfloat162float(__float2bfloat16(v0));
                float h1v = __bfloat162float(__float2bfloat16(v1));
                int widx = tid * 9 + half * 4 + (c >> 1);
                sAh[widx] = pack_bf16x2(h0v, h1v);
                sAl[widx] = pack_bf16x2(v0 - h0v, v1 - h1v);
            }
            if (++kt == 9) { kt = 0; g++; }
        }
        __syncwarp();

        uint32_t ah[2][4], al[2][4];
#pragma unroll
        for (int mt = 0; mt < 2; mt++) {
            int y = 2 * wp + mt;
            int i0 = (y * 16 + qr) * 9 + qc;
            int i1 = (y * 16 + qr + 8) * 9 + qc;
            ah[mt][0] = sAh[i0];
            ah[mt][1] = sAh[i1];
            ah[mt][2] = sAh[i0 + 4];
            ah[mt][3] = sAh[i1 + 4];
            al[mt][0] = sAl[i0];
            al[mt][1] = sAl[i1];
            al[mt][2] = sAl[i0 + 4];
            al[mt][3] = sAl[i1 + 4];
        }
        const uint2* fh = fragH + (size_t)chunk * 256 + lane;
        const uint2* fl = fragL + (size_t)chunk * 256 + lane;
#pragma unroll
        for (int nt = 0; nt < 8; nt++) {
            uint2 bhv2 = __ldg(fh + nt * 32);
            uint2 blv2 = __ldg(fl + nt * 32);
            uint32_t bh[2] = {bhv2.x, bhv2.y};
            uint32_t bl[2] = {blv2.x, blv2.y};
#pragma unroll
            for (int mt = 0; mt < 2; mt++) {
                mma16816(acc[mt][nt], ah[mt], bh);
                mma16816(acc[mt][nt], ah[mt], bl);
                mma16816(acc[mt][nt], al[mt], bh);
            }
        }
        __syncwarp();
    }

#pragma unroll
    for (int mt = 0; mt < 2; mt++) {
        int gy = hy0 + 2 * wp + mt;
        int gx = wx0 + qr;
        int pi = gy * WW + gx;
#pragma unroll
        for (int nt = 0; nt < 8; nt++) {
            int o = nt * 8 + qc * 2;
            float b0 = bdcn[o], b1 = bdcn[o + 1];
            float v0 = acc[mt][nt][0] + b0;
            float v1 = acc[mt][nt][1] + b1;
            float v2 = acc[mt][nt][2] + b0;
            float v3 = acc[mt][nt][3] + b1;
            v0 = (v0 >= 0.f) ? v0 : 0.2f * v0;
            v1 = (v1 >= 0.f) ? v1 : 0.2f * v1;
            v2 = (v2 >= 0.f) ? v2 : 0.2f * v2;
            v3 = (v3 >= 0.f) ? v3 : 0.2f * v3;
            size_t o0i = (size_t)(b * 64 + o) * HW + pi;
            size_t o1i = o0i + HW;
            fea[o0i]     = v0;
            fea[o1i]     = v1;
            fea[o0i + 8] = v2;
            fea[o1i + 8] = v3;
        }
    }
}

// =================================================================
// Launch
// =================================================================
extern "C" void kernel_launch(void* const* d_in, const int* in_sizes, int n_in,
                              void* d_out, int out_size)
{
    const float* x       = (const float*)d_in[0];
    const float* offset  = (const float*)d_in[1];
    const float* w_off   = (const float*)d_in[2];
    const float* b_off   = (const float*)d_in[3];
    const float* w_dcn   = (const float*)d_in[4];
    const float* b_dcn   = (const float*)d_in[5];
    const float* w_conv1 = (const float*)d_in[6];
    const float* b_conv1 = (const float*)d_in[7];
    float* out = (float*)d_out;

    void *p_om, *p_fea, *p_AH, *p_AL, *p_BH, *p_BL, *p_DH, *p_DL;
    cudaGetSymbolAddress(&p_om, g_om);
    cudaGetSymbolAddress(&p_fea, g_fea);
    cudaGetSymbolAddress(&p_AH, g_fAH);
    cudaGetSymbolAddress(&p_AL, g_fAL);
    cudaGetSymbolAddress(&p_BH, g_fBH);
    cudaGetSymbolAddress(&p_BL, g_fBL);
    cudaGetSymbolAddress(&p_DH, g_fDH);
    cudaGetSymbolAddress(&p_DL, g_fDL);
    float* om  = (float*)p_om;
    float* fea = (float*)p_fea;

    const int SMEM_C = 2 * PATCH_BYTES;   // 51840

    cudaFuncSetAttribute((const void*)conv_mma<9, 3, false>,
                         cudaFuncAttributeMaxDynamicSharedMemorySize, SMEM_C);
    cudaFuncSetAttribute((const void*)conv_mma<8, 1, true>,
                         cudaFuncAttributeMaxDynamicSharedMemorySize, SMEM_C);

    // 0) weight prep (fragment packing)
    prep_conv_frag<<<(36 * 27 * 32 + 255) / 256, 256>>>(w_off, (uint2*)p_AH, (uint2*)p_AL, 216);
    prep_conv_frag<<<(36 * 8 * 32 + 255) / 256, 256>>>(w_conv1, (uint2*)p_BH, (uint2*)p_BL, 64);
    prep_wd_frag<<<(36 * 8 * 32 + 255) / 256, 256>>>(w_dcn, (uint2*)p_DH, (uint2*)p_DL);

    // 1) offset conv: 64 -> 216, 3 passes of 72 channels, patch staged once
    conv_mma<9, 3, false><<<dim3(6, 12, BB), 256, SMEM_C>>>(
        offset, (const uint2*)p_AH, (const uint2*)p_AL, b_off, nullptr, om, 216);

    // 2) deformable sampling + grouped einsum + bias + leaky
    deform_mma_k<<<dim3(6, 12, BB), 128>>>(
        x, om, (const uint2*)p_DH, (const uint2*)p_DL, b_dcn, fea);

    // 3) conv1: 64 -> 64 + residual
    conv_mma<8, 1, true><<<dim3(6, 12, BB), 256, SMEM_C>>>(
        fea, (const uint2*)p_BH, (const uint2*)p_BL, b_conv1, x, out, 64);
}

// round 12
// speedup vs baseline: 1.0267x; 1.0267x over previous
#include <cuda_runtime.h>
#include <cuda_bf16.h>
#include <cstdint>
#include <math.h>

// Problem constants
#define HH 96
#define WW 96
#define BB 4
#define CIN 64
#define HW (HH*WW)

// ---------------- scratch (no allocations allowed) ----------------
__device__ float g_om[(size_t)BB * 216 * HW];        // offset-conv output
__device__ float g_fea[(size_t)BB * 64 * HW];        // activated dcn output
__device__ uint4 g_fA[36 * 27 * 32];                 // offset-conv B frags (hi0,hi1,lo0,lo1)
__device__ uint4 g_fB[36 * 8 * 32];                  // conv1 B frags
__device__ uint4 g_fD[36 * 8 * 32];                  // w_dcn B frags

// ---------------- warp MMA: m16n8k16 row.col f32.bf16.bf16.f32 ----------------
__device__ __forceinline__ void mma16816(float* d, const uint32_t* a, const uint32_t* b) {
    asm volatile(
        "mma.sync.aligned.m16n8k16.row.col.f32.bf16.bf16.f32 "
        "{%0,%1,%2,%3}, {%4,%5,%6,%7}, {%8,%9}, {%0,%1,%2,%3};"
        : "+f"(d[0]), "+f"(d[1]), "+f"(d[2]), "+f"(d[3])
        : "r"(a[0]), "r"(a[1]), "r"(a[2]), "r"(a[3]), "r"(b[0]), "r"(b[1]));
}

__device__ __forceinline__ void ldsm_x4(uint32_t* r, uint32_t addr) {
    asm volatile("ldmatrix.sync.aligned.m8n8.x4.shared.b16 {%0,%1,%2,%3}, [%4];"
                 : "=r"(r[0]), "=r"(r[1]), "=r"(r[2]), "=r"(r[3]) : "r"(addr));
}

__device__ __forceinline__ uint32_t smem_u32(const void* p) {
    uint32_t a;
    asm("{ .reg .u64 t; cvta.to.shared.u64 t, %1; cvt.u32.u64 %0, t; }" : "=r"(a) : "l"(p));
    return a;
}

__device__ __forceinline__ uint32_t pack_bf16x2(float a, float b) {
    __nv_bfloat16 ha = __float2bfloat16(a);
    __nv_bfloat16 hb = __float2bfloat16(b);
    return ((uint32_t)__bfloat16_as_ushort(hb) << 16) | (uint32_t)__bfloat16_as_ushort(ha);
}

// =================================================================
// Conv weight prep: fp32 w[Cout][64ci][9tap] -> MMA B fragments packed
// (hi0,hi1,lo0,lo1) per [chunk][ntG][lane]. chunk = tap*4 + kc.
// =================================================================
__global__ void prep_conv_frag(const float* __restrict__ w,
                               uint4* __restrict__ f, int Cout)
{
    int NTOT = Cout >> 3;
    int total = 36 * NTOT * 32;
    int i = blockIdx.x * 256 + threadIdx.x;
    if (i >= total) return;
    int lane = i & 31;
    int ntG  = (i >> 5) % NTOT;
    int chunk = i / (NTOT * 32);
    int tap = chunk >> 2;
    int ci0 = (chunk & 3) * 16;
    int qr = lane >> 2, qc = lane & 3;
    int o = ntG * 8 + qr;
    uint32_t wh[2], wl[2];
#pragma unroll
    for (int half = 0; half < 2; half++) {
        int ci = ci0 + half * 8 + qc * 2;
        float wa = w[(size_t)(o * 64 + ci) * 9 + tap];
        float wb = w[(size_t)(o * 64 + ci + 1) * 9 + tap];
        float ha = __bfloat162float(__float2bfloat16(wa));
        float hb = __bfloat162float(__float2bfloat16(wb));
        wh[half] = pack_bf16x2(ha, hb);
        wl[half] = pack_bf16x2(wa - ha, wb - hb);
    }
    f[i] = make_uint4(wh[0], wh[1], wl[0], wl[1]);
}

// =================================================================
// DCN einsum weight prep: w_dcn[64o][64gc][9k] -> packed B frags.
// chunk covers gk pair (2c, 2c+1).
// =================================================================
__global__ void prep_wd_frag(const float* __restrict__ wdcn, uint4* __restrict__ f)
{
    int i = blockIdx.x * 256 + threadIdx.x;
    if (i >= 36 * 8 * 32) return;
    int lane = i & 31;
    int nt = (i >> 5) & 7;
    int chunk = i >> 8;
    int qr = lane >> 2, qc = lane & 3;
    int o = nt * 8 + qr;
    uint32_t wh[2], wl[2];
#pragma unroll
    for (int half = 0; half < 2; half++) {
        int gk = chunk * 2 + half;
        int g = gk / 9, kt = gk - 9 * g;
        int c = qc * 2;
        float wa = wdcn[(size_t)(o * 64 + g * 8 + c) * 9 + kt];
        float wb = wdcn[(size_t)(o * 64 + g * 8 + c + 1) * 9 + kt];
        float ha = __bfloat162float(__float2bfloat16(wa));
        float hb = __bfloat162float(__float2bfloat16(wb));
        wh[half] = pack_bf16x2(ha, hb);
        wl[half] = pack_bf16x2(wa - ha, wb - hb);
    }
    f[i] = make_uint4(wh[0], wh[1], wl[0], wl[1]);
}

// =================================================================
// 3x3 conv (pad 1, Cin=64) via mma.sync — R9 structure + ldmatrix A +
// uint4-packed B. Block: 128 threads / 4 warps, M=128 px (8x16),
// warp wp -> pixel rows 2wp, 2wp+1 (two m16 tiles). N-chunk via blockIdx.z.
// =================================================================
constexpr int PS = 72;                       // ci stride (elems)
constexpr int PROWB = PS * 2;                // 144 bytes per pixel-row
constexpr int PATCH_BYTES = 180 * PROWB;     // 25920

template<int NT, int NCHUNK, bool RESID>
__global__ __launch_bounds__(128) void conv_mma(
    const float* __restrict__ in,
    const uint4* __restrict__ frag,
    const float* __restrict__ bias, const float* __restrict__ resid,
    float* __restrict__ out, int Cout)
{
    extern __shared__ __align__(16) char smem[];
    __nv_bfloat16* phi = (__nv_bfloat16*)smem;
    __nv_bfloat16* plo = (__nv_bfloat16*)(smem + PATCH_BYTES);

    const int tid  = threadIdx.x;
    const int wp   = tid >> 5;
    const int lane = tid & 31;
    const int qr   = lane >> 2;
    const int qc   = lane & 3;
    // ldmatrix lane roles: r=lane&7, selx=(lane>>3)&1 (x +8), selc=lane>>4 (ci +8)
    const int pxoff  = (lane & 7) + ((lane >> 3) & 1) * 8;
    const int cipart = (lane >> 4) * 8;

    const int wx0 = blockIdx.x * 16;
    const int hy0 = blockIdx.y * 8;
    const int zz  = blockIdx.z;
    const int nc  = zz % NCHUNK;
    const int b   = zz / NCHUNK;
    const int NTOT = Cout >> 3;
    const int co0 = nc * NT * 8;

    const uint32_t sb = smem_u32(smem);

    const float* inb = in + (size_t)b * CIN * HW;
    for (int e = tid; e < 180 * 64; e += 128) {
        int x  = e % 18;
        int y  = (e / 18) % 10;
        int ci = e / 180;
        int gy = hy0 + y - 1;
        int gx = wx0 + x - 1;
        float v = 0.f;
        if ((unsigned)gy < HH && (unsigned)gx < WW)
            v = inb[ci * HW + gy * WW + gx];
        __nv_bfloat16 h = __float2bfloat16(v);
        __nv_bfloat16 l = __float2bfloat16(v - __bfloat162float(h));
        int d = (y * 18 + x) * PS + ci;
        phi[d] = h;
        plo[d] = l;
    }
    __syncthreads();

    float acc[2][NT][4];
#pragma unroll
    for (int mt = 0; mt < 2; mt++)
#pragma unroll
        for (int nt = 0; nt < NT; nt++)
#pragma unroll
            for (int j = 0; j < 4; j++) acc[mt][nt][j] = 0.f;

#pragma unroll 1
    for (int tap = 0; tap < 9; tap++) {
        const int ky = tap / 3, kx = tap % 3;
#pragma unroll
        for (int kc = 0; kc < 4; kc++) {
            const int ci0 = kc * 16;
            uint32_t ah[2][4], al[2][4];
#pragma unroll
            for (int mt = 0; mt < 2; mt++) {
                int row = (2 * wp + mt + ky) * 18 + pxoff + kx;
                uint32_t ad = sb + row * PROWB + (ci0 + cipart) * 2;
                ldsm_x4(ah[mt], ad);
                ldsm_x4(al[mt], ad + PATCH_BYTES);
            }
            const int chunk = tap * 4 + kc;
            const uint4* f = frag + ((size_t)chunk * NTOT + (co0 >> 3)) * 32 + lane;
#pragma unroll
            for (int nt = 0; nt < NT; nt++) {
                uint4 w4 = __ldg(f + nt * 32);
                uint32_t bh[2] = {w4.x, w4.y};
                uint32_t bl[2] = {w4.z, w4.w};
#pragma unroll
                for (int mt = 0; mt < 2; mt++) {
                    mma16816(acc[mt][nt], ah[mt], bh);
                    mma16816(acc[mt][nt], ah[mt], bl);
                    mma16816(acc[mt][nt], al[mt], bh);
                }
            }
        }
    }

#pragma unroll
    for (int mt = 0; mt < 2; mt++) {
        int gy = hy0 + 2 * wp + mt;
        int gx = wx0 + qr;
#pragma unroll
        for (int nt = 0; nt < NT; nt++) {
            int o = co0 + nt * 8 + qc * 2;
            float b0 = bias[o], b1 = bias[o + 1];
            size_t i00 = ((size_t)(b * Cout + o) * HH + gy) * WW + gx;
            size_t i01 = i00 + HW;
            float v0 = acc[mt][nt][0] + b0;
            float v1 = acc[mt][nt][1] + b1;
            float v2 = acc[mt][nt][2] + b0;
            float v3 = acc[mt][nt][3] + b1;
            if (RESID) {
                v0 += resid[i00];     v1 += resid[i01];
                v2 += resid[i00 + 8]; v3 += resid[i01 + 8];
            }
            out[i00] = v0;
            out[i01] = v1;
            out[i00 + 8] = v2;
            out[i01 + 8] = v3;
        }
    }
}

// =================================================================
// Deformable sampling + grouped einsum via mma.sync, fused bias+leaky.
// Warp-private A staging (__syncwarp). B frags now single uint4 LDG.
// =================================================================
__global__ __launch_bounds__(128) void deform_mma_k(
    const float* __restrict__ x, const float* __restrict__ om,
    const uint4* __restrict__ frag,
    const float* __restrict__ bdcn, float* __restrict__ fea)
{
    __shared__ uint32_t sAh[128 * 9];
    __shared__ uint32_t sAl[128 * 9];

    const int tid  = threadIdx.x;
    const int wp   = tid >> 5;
    const int lane = tid & 31;
    const int qr   = lane >> 2;
    const int qc   = lane & 3;
    const int px   = tid & 15;
    const int py   = tid >> 4;

    const int wx0 = blockIdx.x * 16;
    const int hy0 = blockIdx.y * 8;
    const int b   = blockIdx.z;
    const int w0  = wx0 + px;
    const int h0  = hy0 + py;
    const int pidx = h0 * WW + w0;

    const float* omb = om + (size_t)b * 216 * HW;
    const float* xb  = x  + (size_t)b * 64  * HW;

    float acc[2][8][4];
#pragma unroll
    for (int mt = 0; mt < 2; mt++)
#pragma unroll
        for (int nt = 0; nt < 8; nt++)
#pragma unroll
            for (int j = 0; j < 4; j++) acc[mt][nt][j] = 0.f;

    int g = 0, kt = 0;

#pragma unroll 1
    for (int chunk = 0; chunk < 36; chunk++) {
#pragma unroll
        for (int half = 0; half < 2; half++) {
            const int gk = chunk * 2 + half;
            float oy = __ldg(&omb[(size_t)gk * HW + pidx]);
            float ox = __ldg(&omb[(size_t)(72 + gk) * HW + pidx]);
            float ml = __ldg(&omb[(size_t)(144 + gk) * HW + pidx]);
            float m  = 1.f / (1.f + __expf(-ml));

            float pyf = (float)(h0 + kt / 3 - 1) + oy;
            float pxf = (float)(w0 + kt % 3 - 1) + ox;
            float y0f = floorf(pyf), x0f = floorf(pxf);
            float fy = pyf - y0f, fx = pxf - x0f;
            int y0 = (int)y0f, x0 = (int)x0f;
            int y1 = y0 + 1,  x1 = x0 + 1;

            float vy0 = (y0 >= 0 && y0 < HH) ? 1.f : 0.f;
            float vy1 = (y1 >= 0 && y1 < HH) ? 1.f : 0.f;
            float vx0 = (x0 >= 0 && x0 < WW) ? 1.f : 0.f;
            float vx1 = (x1 >= 0 && x1 < WW) ? 1.f : 0.f;
            int yc0 = min(max(y0, 0), HH - 1);
            int yc1 = min(max(y1, 0), HH - 1);
            int xc0 = min(max(x0, 0), WW - 1);
            int xc1 = min(max(x1, 0), WW - 1);

            float w00 = (1.f - fy) * (1.f - fx) * vy0 * vx0 * m;
            float w01 = (1.f - fy) * fx        * vy0 * vx1 * m;
            float w10 = fy        * (1.f - fx) * vy1 * vx0 * m;
            float w11 = fy        * fx         * vy1 * vx1 * m;

            int i00 = yc0 * WW + xc0;
            int i01 = yc0 * WW + xc1;
            int i10 = yc1 * WW + xc0;
            int i11 = yc1 * WW + xc1;

            const float* xg = xb + g * 8 * HW;
#pragma unroll
            for (int c = 0; c < 8; c += 2) {
                const float* xc0p = xg + c * HW;
                const float* xc1p = xg + (c + 1) * HW;
                float v0 = w00 * __ldg(xc0p + i00) + w01 * __ldg(xc0p + i01)
                         + w10 * __ldg(xc0p + i10) + w11 * __ldg(xc0p + i11);
                float v1 = w00 * __ldg(xc1p + i00) + w01 * __ldg(xc1p + i01)
                         + w10 * __ldg(xc1p + i10) + w11 * __ldg(xc1p + i11);
                float h0v = __bfloat162float(__float2bfloat16(v0));
                float h1v = __bfloat162float(__float2bfloat16(v1));
                int widx = tid * 9 + half * 4 + (c >> 1);
                sAh[widx] = pack_bf16x2(h0v, h1v);
                sAl[widx] = pack_bf16x2(v0 - h0v, v1 - h1v);
            }
            if (++kt == 9) { kt = 0; g++; }
        }
        __syncwarp();

        uint32_t ah[2][4], al[2][4];
#pragma unroll
        for (int mt = 0; mt < 2; mt++) {
            int y = 2 * wp + mt;
            int i0 = (y * 16 + qr) * 9 + qc;
            int i1 = (y * 16 + qr + 8) * 9 + qc;
            ah[mt][0] = sAh[i0];
            ah[mt][1] = sAh[i1];
            ah[mt][2] = sAh[i0 + 4];
            ah[mt][3] = sAh[i1 + 4];
            al[mt][0] = sAl[i0];
            al[mt][1] = sAl[i1];
            al[mt][2] = sAl[i0 + 4];
            al[mt][3] = sAl[i1 + 4];
        }
        const uint4* f = frag + (size_t)chunk * 256 + lane;
#pragma unroll
        for (int nt = 0; nt < 8; nt++) {
            uint4 w4 = __ldg(f + nt * 32);
            uint32_t bh[2] = {w4.x, w4.y};
            uint32_t bl[2] = {w4.z, w4.w};
#pragma unroll
            for (int mt = 0; mt < 2; mt++) {
                mma16816(acc[mt][nt], ah[mt], bh);
                mma16816(acc[mt][nt], ah[mt], bl);
                mma16816(acc[mt][nt], al[mt], bh);
            }
        }
        __syncwarp();
    }

#pragma unroll
    for (int mt = 0; mt < 2; mt++) {
        int gy = hy0 + 2 * wp + mt;
        int gx = wx0 + qr;
        int pi = gy * WW + gx;
#pragma unroll
        for (int nt = 0; nt < 8; nt++) {
            int o = nt * 8 + qc * 2;
            float b0 = bdcn[o], b1 = bdcn[o + 1];
            float v0 = acc[mt][nt][0] + b0;
            float v1 = acc[mt][nt][1] + b1;
            float v2 = acc[mt][nt][2] + b0;
            float v3 = acc[mt][nt][3] + b1;
            v0 = (v0 >= 0.f) ? v0 : 0.2f * v0;
            v1 = (v1 >= 0.f) ? v1 : 0.2f * v1;
            v2 = (v2 >= 0.f) ? v2 : 0.2f * v2;
            v3 = (v3 >= 0.f) ? v3 : 0.2f * v3;
            size_t o0i = (size_t)(b * 64 + o) * HW + pi;
            size_t o1i = o0i + HW;
            fea[o0i]     = v0;
            fea[o1i]     = v1;
            fea[o0i + 8] = v2;
            fea[o1i + 8] = v3;
        }
    }
}

// =================================================================
// Launch
// =================================================================
extern "C" void kernel_launch(void* const* d_in, const int* in_sizes, int n_in,
                              void* d_out, int out_size)
{
    const float* x       = (const float*)d_in[0];
    const float* offset  = (const float*)d_in[1];
    const float* w_off   = (const float*)d_in[2];
    const float* b_off   = (const float*)d_in[3];
    const float* w_dcn   = (const float*)d_in[4];
    const float* b_dcn   = (const float*)d_in[5];
    const float* w_conv1 = (const float*)d_in[6];
    const float* b_conv1 = (const float*)d_in[7];
    float* out = (float*)d_out;

    void *p_om, *p_fea, *p_A, *p_B, *p_D;
    cudaGetSymbolAddress(&p_om, g_om);
    cudaGetSymbolAddress(&p_fea, g_fea);
    cudaGetSymbolAddress(&p_A, g_fA);
    cudaGetSymbolAddress(&p_B, g_fB);
    cudaGetSymbolAddress(&p_D, g_fD);
    float* om  = (float*)p_om;
    float* fea = (float*)p_fea;

    const int SMEM_C = 2 * PATCH_BYTES;   // 51840

    cudaFuncSetAttribute((const void*)conv_mma<9, 3, false>,
                         cudaFuncAttributeMaxDynamicSharedMemorySize, SMEM_C);
    cudaFuncSetAttribute((const void*)conv_mma<8, 1, true>,
                         cudaFuncAttributeMaxDynamicSharedMemorySize, SMEM_C);

    // 0) weight prep (fragment packing)
    prep_conv_frag<<<(36 * 27 * 32 + 255) / 256, 256>>>(w_off, (uint4*)p_A, 216);
    prep_conv_frag<<<(36 * 8 * 32 + 255) / 256, 256>>>(w_conv1, (uint4*)p_B, 64);
    prep_wd_frag<<<(36 * 8 * 32 + 255) / 256, 256>>>(w_dcn, (uint4*)p_D);

    // 1) offset conv: 64 -> 216, 3 N-chunks via blockIdx.z
    conv_mma<9, 3, false><<<dim3(6, 12, BB * 3), 128, SMEM_C>>>(
        offset, (const uint4*)p_A, b_off, nullptr, om, 216);

    // 2) deformable sampling + grouped einsum + bias + leaky
    deform_mma_k<<<dim3(6, 12, BB), 128>>>(
        x, om, (const uint4*)p_D, b_dcn, fea);

    // 3) conv1: 64 -> 64 + residual
    conv_mma<8, 1, true><<<dim3(6, 12, BB), 128, SMEM_C>>>(
        fea, (const uint4*)p_B, b_conv1, x, out, 64);
}

// round 13
// speedup vs baseline: 1.2227x; 1.1909x over previous
#include <cuda_runtime.h>
#include <cuda_bf16.h>
#include <cstdint>
#include <math.h>

// Problem constants
#define HH 96
#define WW 96
#define BB 4
#define CIN 64
#define HW (HH*WW)

// ---------------- scratch (no allocations allowed) ----------------
__device__ float g_om[(size_t)BB * 216 * HW];        // offset-conv output
__device__ float g_fea[(size_t)BB * 64 * HW];        // activated dcn output
__device__ uint4 g_fA[36 * 27 * 32];                 // offset-conv B frags (hi0,hi1,lo0,lo1)
__device__ uint4 g_fB[36 * 8 * 32];                  // conv1 B frags
__device__ uint2 g_fDH[36 * 8 * 32];                 // w_dcn B frags hi
__device__ uint2 g_fDL[36 * 8 * 32];                 // lo

// ---------------- warp MMA: m16n8k16 row.col f32.bf16.bf16.f32 ----------------
__device__ __forceinline__ void mma16816(float* d, const uint32_t* a, const uint32_t* b) {
    asm volatile(
        "mma.sync.aligned.m16n8k16.row.col.f32.bf16.bf16.f32 "
        "{%0,%1,%2,%3}, {%4,%5,%6,%7}, {%8,%9}, {%0,%1,%2,%3};"
        : "+f"(d[0]), "+f"(d[1]), "+f"(d[2]), "+f"(d[3])
        : "r"(a[0]), "r"(a[1]), "r"(a[2]), "r"(a[3]), "r"(b[0]), "r"(b[1]));
}

__device__ __forceinline__ void ldsm_x4(uint32_t* r, uint32_t addr) {
    asm volatile("ldmatrix.sync.aligned.m8n8.x4.shared.b16 {%0,%1,%2,%3}, [%4];"
                 : "=r"(r[0]), "=r"(r[1]), "=r"(r[2]), "=r"(r[3]) : "r"(addr));
}

__device__ __forceinline__ uint32_t smem_u32(const void* p) {
    uint32_t a;
    asm("{ .reg .u64 t; cvta.to.shared.u64 t, %1; cvt.u32.u64 %0, t; }" : "=r"(a) : "l"(p));
    return a;
}

__device__ __forceinline__ uint32_t pack_bf16x2(float a, float b) {
    __nv_bfloat16 ha = __float2bfloat16(a);
    __nv_bfloat16 hb = __float2bfloat16(b);
    return ((uint32_t)__bfloat16_as_ushort(hb) << 16) | (uint32_t)__bfloat16_as_ushort(ha);
}

// =================================================================
// Conv weight prep: fp32 w[Cout][64ci][9tap] -> MMA B fragments packed
// (hi0,hi1,lo0,lo1) per [chunk][ntG][lane]. chunk = tap*4 + kc.
// =================================================================
__global__ void prep_conv_frag(const float* __restrict__ w,
                               uint4* __restrict__ f, int Cout)
{
    int NTOT = Cout >> 3;
    int total = 36 * NTOT * 32;
    int i = blockIdx.x * 256 + threadIdx.x;
    if (i >= total) return;
    int lane = i & 31;
    int ntG  = (i >> 5) % NTOT;
    int chunk = i / (NTOT * 32);
    int tap = chunk >> 2;
    int ci0 = (chunk & 3) * 16;
    int qr = lane >> 2, qc = lane & 3;
    int o = ntG * 8 + qr;
    uint32_t wh[2], wl[2];
#pragma unroll
    for (int half = 0; half < 2; half++) {
        int ci = ci0 + half * 8 + qc * 2;
        float wa = w[(size_t)(o * 64 + ci) * 9 + tap];
        float wb = w[(size_t)(o * 64 + ci + 1) * 9 + tap];
        float ha = __bfloat162float(__float2bfloat16(wa));
        float hb = __bfloat162float(__float2bfloat16(wb));
        wh[half] = pack_bf16x2(ha, hb);
        wl[half] = pack_bf16x2(wa - ha, wb - hb);
    }
    f[i] = make_uint4(wh[0], wh[1], wl[0], wl[1]);
}

// =================================================================
// DCN einsum weight prep: w_dcn[64o][64gc][9k] -> per-chunk B frags
// (uint2 hi / uint2 lo, separate arrays — R9-proven layout).
// =================================================================
__global__ void prep_wd_frag(const float* __restrict__ wdcn,
                             uint2* __restrict__ fh, uint2* __restrict__ fl)
{
    int i = blockIdx.x * 256 + threadIdx.x;
    if (i >= 36 * 8 * 32) return;
    int lane = i & 31;
    int nt = (i >> 5) & 7;
    int chunk = i >> 8;
    int qr = lane >> 2, qc = lane & 3;
    int o = nt * 8 + qr;
    uint32_t wh[2], wl[2];
#pragma unroll
    for (int half = 0; half < 2; half++) {
        int gk = chunk * 2 + half;
        int g = gk / 9, kt = gk - 9 * g;
        int c = qc * 2;
        float wa = wdcn[(size_t)(o * 64 + g * 8 + c) * 9 + kt];
        float wb = wdcn[(size_t)(o * 64 + g * 8 + c + 1) * 9 + kt];
        float ha = __bfloat162float(__float2bfloat16(wa));
        float hb = __bfloat162float(__float2bfloat16(wb));
        wh[half] = pack_bf16x2(ha, hb);
        wl[half] = pack_bf16x2(wa - ha, wb - hb);
    }
    fh[i] = make_uint2(wh[0], wh[1]);
    fl[i] = make_uint2(wl[0], wl[1]);
}

// =================================================================
// 3x3 conv (pad 1, Cin=64) via mma.sync — ldmatrix A + uint4-packed B.
// Block: 128 threads / 4 warps, M=128 px (8x16),
// warp wp -> pixel rows 2wp, 2wp+1 (two m16 tiles). N-chunk via blockIdx.z.
// =================================================================
constexpr int PS = 72;                       // ci stride (elems)
constexpr int PROWB = PS * 2;                // 144 bytes per pixel-row
constexpr int PATCH_BYTES = 180 * PROWB;     // 25920

template<int NT, int NCHUNK, bool RESID>
__global__ __launch_bounds__(128) void conv_mma(
    const float* __restrict__ in,
    const uint4* __restrict__ frag,
    const float* __restrict__ bias, const float* __restrict__ resid,
    float* __restrict__ out, int Cout)
{
    extern __shared__ __align__(16) char smem[];
    __nv_bfloat16* phi = (__nv_bfloat16*)smem;
    __nv_bfloat16* plo = (__nv_bfloat16*)(smem + PATCH_BYTES);

    const int tid  = threadIdx.x;
    const int wp   = tid >> 5;
    const int lane = tid & 31;
    const int qr   = lane >> 2;
    const int qc   = lane & 3;
    const int pxoff  = (lane & 7) + ((lane >> 3) & 1) * 8;
    const int cipart = (lane >> 4) * 8;

    const int wx0 = blockIdx.x * 16;
    const int hy0 = blockIdx.y * 8;
    const int zz  = blockIdx.z;
    const int nc  = zz % NCHUNK;
    const int b   = zz / NCHUNK;
    const int NTOT = Cout >> 3;
    const int co0 = nc * NT * 8;

    const uint32_t sb = smem_u32(smem);

    const float* inb = in + (size_t)b * CIN * HW;
    for (int e = tid; e < 180 * 64; e += 128) {
        int x  = e % 18;
        int y  = (e / 18) % 10;
        int ci = e / 180;
        int gy = hy0 + y - 1;
        int gx = wx0 + x - 1;
        float v = 0.f;
        if ((unsigned)gy < HH && (unsigned)gx < WW)
            v = inb[ci * HW + gy * WW + gx];
        __nv_bfloat16 h = __float2bfloat16(v);
        __nv_bfloat16 l = __float2bfloat16(v - __bfloat162float(h));
        int d = (y * 18 + x) * PS + ci;
        phi[d] = h;
        plo[d] = l;
    }
    __syncthreads();

    float acc[2][NT][4];
#pragma unroll
    for (int mt = 0; mt < 2; mt++)
#pragma unroll
        for (int nt = 0; nt < NT; nt++)
#pragma unroll
            for (int j = 0; j < 4; j++) acc[mt][nt][j] = 0.f;

#pragma unroll 1
    for (int tap = 0; tap < 9; tap++) {
        const int ky = tap / 3, kx = tap % 3;
#pragma unroll
        for (int kc = 0; kc < 4; kc++) {
            const int ci0 = kc * 16;
            uint32_t ah[2][4], al[2][4];
#pragma unroll
            for (int mt = 0; mt < 2; mt++) {
                int row = (2 * wp + mt + ky) * 18 + pxoff + kx;
                uint32_t ad = sb + row * PROWB + (ci0 + cipart) * 2;
                ldsm_x4(ah[mt], ad);
                ldsm_x4(al[mt], ad + PATCH_BYTES);
            }
            const int chunk = tap * 4 + kc;
            const uint4* f = frag + ((size_t)chunk * NTOT + (co0 >> 3)) * 32 + lane;
#pragma unroll
            for (int nt = 0; nt < NT; nt++) {
                uint4 w4 = __ldg(f + nt * 32);
                uint32_t bh[2] = {w4.x, w4.y};
                uint32_t bl[2] = {w4.z, w4.w};
#pragma unroll
                for (int mt = 0; mt < 2; mt++) {
                    mma16816(acc[mt][nt], ah[mt], bh);
                    mma16816(acc[mt][nt], ah[mt], bl);
                    mma16816(acc[mt][nt], al[mt], bh);
                }
            }
        }
    }

#pragma unroll
    for (int mt = 0; mt < 2; mt++) {
        int gy = hy0 + 2 * wp + mt;
        int gx = wx0 + qr;
#pragma unroll
        for (int nt = 0; nt < NT; nt++) {
            int o = co0 + nt * 8 + qc * 2;
            float b0 = bias[o], b1 = bias[o + 1];
            size_t i00 = ((size_t)(b * Cout + o) * HH + gy) * WW + gx;
            size_t i01 = i00 + HW;
            float v0 = acc[mt][nt][0] + b0;
            float v1 = acc[mt][nt][1] + b1;
            float v2 = acc[mt][nt][2] + b0;
            float v3 = acc[mt][nt][3] + b1;
            if (RESID) {
                v0 += resid[i00];     v1 += resid[i01];
                v2 += resid[i00 + 8]; v3 += resid[i01 + 8];
            }
            out[i00] = v0;
            out[i01] = v1;
            out[i00 + 8] = v2;
            out[i01 + 8] = v3;
        }
    }
}

// =================================================================
// Deformable sampling + grouped einsum via mma.sync, fused bias+leaky.
// R9-proven: warp-private A staging (__syncwarp), uint2 hi/lo B frags.
// =================================================================
__global__ __launch_bounds__(128) void deform_mma_k(
    const float* __restrict__ x, const float* __restrict__ om,
    const uint2* __restrict__ fragH, const uint2* __restrict__ fragL,
    const float* __restrict__ bdcn, float* __restrict__ fea)
{
    __shared__ uint32_t sAh[128 * 9];
    __shared__ uint32_t sAl[128 * 9];

    const int tid  = threadIdx.x;
    const int wp   = tid >> 5;
    const int lane = tid & 31;
    const int qr   = lane >> 2;
    const int qc   = lane & 3;
    const int px   = tid & 15;
    const int py   = tid >> 4;

    const int wx0 = blockIdx.x * 16;
    const int hy0 = blockIdx.y * 8;
    const int b   = blockIdx.z;
    const int w0  = wx0 + px;
    const int h0  = hy0 + py;
    const int pidx = h0 * WW + w0;

    const float* omb = om + (size_t)b * 216 * HW;
    const float* xb  = x  + (size_t)b * 64  * HW;

    float acc[2][8][4];
#pragma unroll
    for (int mt = 0; mt < 2; mt++)
#pragma unroll
        for (int nt = 0; nt < 8; nt++)
#pragma unroll
            for (int j = 0; j < 4; j++) acc[mt][nt][j] = 0.f;

    int g = 0, kt = 0;

#pragma unroll 1
    for (int chunk = 0; chunk < 36; chunk++) {
#pragma unroll
        for (int half = 0; half < 2; half++) {
            const int gk = chunk * 2 + half;
            float oy = __ldg(&omb[(size_t)gk * HW + pidx]);
            float ox = __ldg(&omb[(size_t)(72 + gk) * HW + pidx]);
            float ml = __ldg(&omb[(size_t)(144 + gk) * HW + pidx]);
            float m  = 1.f / (1.f + __expf(-ml));

            float pyf = (float)(h0 + kt / 3 - 1) + oy;
            float pxf = (float)(w0 + kt % 3 - 1) + ox;
            float y0f = floorf(pyf), x0f = floorf(pxf);
            float fy = pyf - y0f, fx = pxf - x0f;
            int y0 = (int)y0f, x0 = (int)x0f;
            int y1 = y0 + 1,  x1 = x0 + 1;

            float vy0 = (y0 >= 0 && y0 < HH) ? 1.f : 0.f;
            float vy1 = (y1 >= 0 && y1 < HH) ? 1.f : 0.f;
            float vx0 = (x0 >= 0 && x0 < WW) ? 1.f : 0.f;
            float vx1 = (x1 >= 0 && x1 < WW) ? 1.f : 0.f;
            int yc0 = min(max(y0, 0), HH - 1);
            int yc1 = min(max(y1, 0), HH - 1);
            int xc0 = min(max(x0, 0), WW - 1);
            int xc1 = min(max(x1, 0), WW - 1);

            float w00 = (1.f - fy) * (1.f - fx) * vy0 * vx0 * m;
            float w01 = (1.f - fy) * fx        * vy0 * vx1 * m;
            float w10 = fy        * (1.f - fx) * vy1 * vx0 * m;
            float w11 = fy        * fx         * vy1 * vx1 * m;

            int i00 = yc0 * WW + xc0;
            int i01 = yc0 * WW + xc1;
            int i10 = yc1 * WW + xc0;
            int i11 = yc1 * WW + xc1;

            const float* xg = xb + g * 8 * HW;
#pragma unroll
            for (int c = 0; c < 8; c += 2) {
                const float* xc0p = xg + c * HW;
                const float* xc1p = xg + (c + 1) * HW;
                float v0 = w00 * __ldg(xc0p + i00) + w01 * __ldg(xc0p + i01)
                         + w10 * __ldg(xc0p + i10) + w11 * __ldg(xc0p + i11);
                float v1 = w00 * __ldg(xc1p + i00) + w01 * __ldg(xc1p + i01)
                         + w10 * __ldg(xc1p + i10) + w11 * __ldg(xc1p + i11);
                float h0v = __bfloat162float(__float2bfloat16(v0));
                float h1v = __bfloat162float(__float2bfloat16(v1));
                int widx = tid * 9 + half * 4 + (c >> 1);
                sAh[widx] = pack_bf16x2(h0v, h1v);
                sAl[widx] = pack_bf16x2(v0 - h0v, v1 - h1v);
            }
            if (++kt == 9) { kt = 0; g++; }
        }
        __syncwarp();

        uint32_t ah[2][4], al[2][4];
#pragma unroll
        for (int mt = 0; mt < 2; mt++) {
            int y = 2 * wp + mt;
            int i0 = (y * 16 + qr) * 9 + qc;
            int i1 = (y * 16 + qr + 8) * 9 + qc;
            ah[mt][0] = sAh[i0];
            ah[mt][1] = sAh[i1];
            ah[mt][2] = sAh[i0 + 4];
            ah[mt][3] = sAh[i1 + 4];
            al[mt][0] = sAl[i0];
            al[mt][1] = sAl[i1];
            al[mt][2] = sAl[i0 + 4];
            al[mt][3] = sAl[i1 + 4];
        }
        const uint2* fh = fragH + (size_t)chunk * 256 + lane;
        const uint2* fl = fragL + (size_t)chunk * 256 + lane;
#pragma unroll
        for (int nt = 0; nt < 8; nt++) {
            uint2 bhv2 = __ldg(fh + nt * 32);
            uint2 blv2 = __ldg(fl + nt * 32);
            uint32_t bh[2] = {bhv2.x, bhv2.y};
            uint32_t bl[2] = {blv2.x, blv2.y};
#pragma unroll
            for (int mt = 0; mt < 2; mt++) {
                mma16816(acc[mt][nt], ah[mt], bh);
                mma16816(acc[mt][nt], ah[mt], bl);
                mma16816(acc[mt][nt], al[mt], bh);
            }
        }
        __syncwarp();
    }

#pragma unroll
    for (int mt = 0; mt < 2; mt++) {
        int gy = hy0 + 2 * wp + mt;
        int gx = wx0 + qr;
        int pi = gy * WW + gx;
#pragma unroll
        for (int nt = 0; nt < 8; nt++) {
            int o = nt * 8 + qc * 2;
            float b0 = bdcn[o], b1 = bdcn[o + 1];
            float v0 = acc[mt][nt][0] + b0;
            float v1 = acc[mt][nt][1] + b1;
            float v2 = acc[mt][nt][2] + b0;
            float v3 = acc[mt][nt][3] + b1;
            v0 = (v0 >= 0.f) ? v0 : 0.2f * v0;
            v1 = (v1 >= 0.f) ? v1 : 0.2f * v1;
            v2 = (v2 >= 0.f) ? v2 : 0.2f * v2;
            v3 = (v3 >= 0.f) ? v3 : 0.2f * v3;
            size_t o0i = (size_t)(b * 64 + o) * HW + pi;
            size_t o1i = o0i + HW;
            fea[o0i]     = v0;
            fea[o1i]     = v1;
            fea[o0i + 8] = v2;
            fea[o1i + 8] = v3;
        }
    }
}

// =================================================================
// Launch
// =================================================================
extern "C" void kernel_launch(void* const* d_in, const int* in_sizes, int n_in,
                              void* d_out, int out_size)
{
    const float* x       = (const float*)d_in[0];
    const float* offset  = (const float*)d_in[1];
    const float* w_off   = (const float*)d_in[2];
    const float* b_off   = (const float*)d_in[3];
    const float* w_dcn   = (const float*)d_in[4];
    const float* b_dcn   = (const float*)d_in[5];
    const float* w_conv1 = (const float*)d_in[6];
    const float* b_conv1 = (const float*)d_in[7];
    float* out = (float*)d_out;

    void *p_om, *p_fea, *p_A, *p_B, *p_DH, *p_DL;
    cudaGetSymbolAddress(&p_om, g_om);
    cudaGetSymbolAddress(&p_fea, g_fea);
    cudaGetSymbolAddress(&p_A, g_fA);
    cudaGetSymbolAddress(&p_B, g_fB);
    cudaGetSymbolAddress(&p_DH, g_fDH);
    cudaGetSymbolAddress(&p_DL, g_fDL);
    float* om  = (float*)p_om;
    float* fea = (float*)p_fea;

    const int SMEM_C = 2 * PATCH_BYTES;   // 51840

    cudaFuncSetAttribute((const void*)conv_mma<9, 3, false>,
                         cudaFuncAttributeMaxDynamicSharedMemorySize, SMEM_C);
    cudaFuncSetAttribute((const void*)conv_mma<8, 1, true>,
                         cudaFuncAttributeMaxDynamicSharedMemorySize, SMEM_C);

    // 0) weight prep (fragment packing)
    prep_conv_frag<<<(36 * 27 * 32 + 255) / 256, 256>>>(w_off, (uint4*)p_A, 216);
    prep_conv_frag<<<(36 * 8 * 32 + 255) / 256, 256>>>(w_conv1, (uint4*)p_B, 64);
    prep_wd_frag<<<(36 * 8 * 32 + 255) / 256, 256>>>(w_dcn, (uint2*)p_DH, (uint2*)p_DL);

    // 1) offset conv: 64 -> 216, 3 N-chunks via blockIdx.z
    conv_mma<9, 3, false><<<dim3(6, 12, BB * 3), 128, SMEM_C>>>(
        offset, (const uint4*)p_A, b_off, nullptr, om, 216);

    // 2) deformable sampling + grouped einsum + bias + leaky
    deform_mma_k<<<dim3(6, 12, BB), 128>>>(
        x, om, (const uint2*)p_DH, (const uint2*)p_DL, b_dcn, fea);

    // 3) conv1: 64 -> 64 + residual
    conv_mma<8, 1, true><<<dim3(6, 12, BB), 128, SMEM_C>>>(
        fea, (const uint4*)p_B, b_conv1, x, out, 64);
}

// round 15
// speedup vs baseline: 1.3276x; 1.0858x over previous
#include <cuda_runtime.h>
#include <cuda_bf16.h>
#include <cstdint>
#include <math.h>

// Problem constants
#define HH 96
#define WW 96
#define BB 4
#define CIN 64
#define HW (HH*WW)

// ---------------- scratch (no allocations allowed) ----------------
__device__ float g_om[(size_t)BB * 216 * HW];        // offset-conv output
__device__ float g_fea[(size_t)BB * 64 * HW];        // activated dcn output
__device__ uint4 g_fA[36 * 27 * 32];                 // offset-conv B frags (hi0,hi1,lo0,lo1)
__device__ uint4 g_fB[36 * 8 * 32];                  // conv1 B frags
__device__ uint2 g_fDH[36 * 8 * 32];                 // w_dcn B frags hi
__device__ uint2 g_fDL[36 * 8 * 32];                 // lo

// ---------------- warp MMA: m16n8k16 row.col f32.bf16.bf16.f32 ----------------
__device__ __forceinline__ void mma16816(float* d, const uint32_t* a, const uint32_t* b) {
    asm volatile(
        "mma.sync.aligned.m16n8k16.row.col.f32.bf16.bf16.f32 "
        "{%0,%1,%2,%3}, {%4,%5,%6,%7}, {%8,%9}, {%0,%1,%2,%3};"
        : "+f"(d[0]), "+f"(d[1]), "+f"(d[2]), "+f"(d[3])
        : "r"(a[0]), "r"(a[1]), "r"(a[2]), "r"(a[3]), "r"(b[0]), "r"(b[1]));
}

__device__ __forceinline__ void ldsm_x4(uint32_t* r, uint32_t addr) {
    asm volatile("ldmatrix.sync.aligned.m8n8.x4.shared.b16 {%0,%1,%2,%3}, [%4];"
                 : "=r"(r[0]), "=r"(r[1]), "=r"(r[2]), "=r"(r[3]) : "r"(addr));
}

__device__ __forceinline__ uint32_t smem_u32(const void* p) {
    uint32_t a;
    asm("{ .reg .u64 t; cvta.to.shared.u64 t, %1; cvt.u32.u64 %0, t; }" : "=r"(a) : "l"(p));
    return a;
}

__device__ __forceinline__ uint32_t pack_bf16x2(float a, float b) {
    __nv_bfloat16 ha = __float2bfloat16(a);
    __nv_bfloat16 hb = __float2bfloat16(b);
    return ((uint32_t)__bfloat16_as_ushort(hb) << 16) | (uint32_t)__bfloat16_as_ushort(ha);
}

// =================================================================
// Conv weight prep: fp32 w[Cout][64ci][9tap] -> MMA B fragments packed
// (hi0,hi1,lo0,lo1) per [chunk][ntG][lane]. chunk = tap*4 + kc.
// =================================================================
__global__ void prep_conv_frag(const float* __restrict__ w,
                               uint4* __restrict__ f, int Cout)
{
    int NTOT = Cout >> 3;
    int total = 36 * NTOT * 32;
    int i = blockIdx.x * 256 + threadIdx.x;
    if (i >= total) return;
    int lane = i & 31;
    int ntG  = (i >> 5) % NTOT;
    int chunk = i / (NTOT * 32);
    int tap = chunk >> 2;
    int ci0 = (chunk & 3) * 16;
    int qr = lane >> 2, qc = lane & 3;
    int o = ntG * 8 + qr;
    uint32_t wh[2], wl[2];
#pragma unroll
    for (int half = 0; half < 2; half++) {
        int ci = ci0 + half * 8 + qc * 2;
        float wa = w[(size_t)(o * 64 + ci) * 9 + tap];
        float wb = w[(size_t)(o * 64 + ci + 1) * 9 + tap];
        float ha = __bfloat162float(__float2bfloat16(wa));
        float hb = __bfloat162float(__float2bfloat16(wb));
        wh[half] = pack_bf16x2(ha, hb);
        wl[half] = pack_bf16x2(wa - ha, wb - hb);
    }
    f[i] = make_uint4(wh[0], wh[1], wl[0], wl[1]);
}

// =================================================================
// DCN einsum weight prep: w_dcn[64o][64gc][9k] -> per-chunk B frags
// (uint2 hi / uint2 lo, separate arrays — R9-proven layout).
// =================================================================
__global__ void prep_wd_frag(const float* __restrict__ wdcn,
                             uint2* __restrict__ fh, uint2* __restrict__ fl)
{
    int i = blockIdx.x * 256 + threadIdx.x;
    if (i >= 36 * 8 * 32) return;
    int lane = i & 31;
    int nt = (i >> 5) & 7;
    int chunk = i >> 8;
    int qr = lane >> 2, qc = lane & 3;
    int o = nt * 8 + qr;
    uint32_t wh[2], wl[2];
#pragma unroll
    for (int half = 0; half < 2; half++) {
        int gk = chunk * 2 + half;
        int g = gk / 9, kt = gk - 9 * g;
        int c = qc * 2;
        float wa = wdcn[(size_t)(o * 64 + g * 8 + c) * 9 + kt];
        float wb = wdcn[(size_t)(o * 64 + g * 8 + c + 1) * 9 + kt];
        float ha = __bfloat162float(__float2bfloat16(wa));
        float hb = __bfloat162float(__float2bfloat16(wb));
        wh[half] = pack_bf16x2(ha, hb);
        wl[half] = pack_bf16x2(wa - ha, wb - hb);
    }
    fh[i] = make_uint2(wh[0], wh[1]);
    fl[i] = make_uint2(wl[0], wl[1]);
}

// =================================================================
// 3x3 conv (pad 1, Cin=64) via mma.sync — ldmatrix A + uint4-packed B.
// Block: 128 threads / 4 warps, M=128 px (8x16), warp wp -> pixel rows
// 2wp, 2wp+1 (two m16 tiles). N covered by NPASS in-block passes
// (patch staged ONCE). Flattened 36-chunk loop, unroll 2 so ptxas can
// overlap chunk i+1 loads with chunk i HMMAs.
// =================================================================
constexpr int PS = 72;                       // ci stride (elems)
constexpr int PROWB = PS * 2;                // 144 bytes per pixel-row
constexpr int PATCH_BYTES = 180 * PROWB;     // 25920

template<int NT, int NPASS, bool RESID>
__global__ __launch_bounds__(128, 3) void conv_mma(
    const float* __restrict__ in,
    const uint4* __restrict__ frag,
    const float* __restrict__ bias, const float* __restrict__ resid,
    float* __restrict__ out, int Cout)
{
    extern __shared__ __align__(16) char smem[];
    __nv_bfloat16* phi = (__nv_bfloat16*)smem;
    __nv_bfloat16* plo = (__nv_bfloat16*)(smem + PATCH_BYTES);

    const int tid  = threadIdx.x;
    const int wp   = tid >> 5;
    const int lane = tid & 31;
    const int qr   = lane >> 2;
    const int qc   = lane & 3;
    const int pxoff  = (lane & 7) + ((lane >> 3) & 1) * 8;
    const int cipart = (lane >> 4) * 8;

    const int wx0 = blockIdx.x * 16;
    const int hy0 = blockIdx.y * 8;
    const int b   = blockIdx.z;
    const int NTOT = Cout >> 3;

    const uint32_t sb = smem_u32(smem);

    const float* inb = in + (size_t)b * CIN * HW;
    for (int e = tid; e < 180 * 64; e += 128) {
        int x  = e % 18;
        int y  = (e / 18) % 10;
        int ci = e / 180;
        int gy = hy0 + y - 1;
        int gx = wx0 + x - 1;
        float v = 0.f;
        if ((unsigned)gy < HH && (unsigned)gx < WW)
            v = inb[ci * HW + gy * WW + gx];
        __nv_bfloat16 h = __float2bfloat16(v);
        __nv_bfloat16 l = __float2bfloat16(v - __bfloat162float(h));
        int d = (y * 18 + x) * PS + ci;
        phi[d] = h;
        plo[d] = l;
    }
    __syncthreads();

#pragma unroll 1
    for (int pass = 0; pass < NPASS; pass++) {
        const int co0 = pass * NT * 8;

        float acc[2][NT][4];
#pragma unroll
        for (int mt = 0; mt < 2; mt++)
#pragma unroll
            for (int nt = 0; nt < NT; nt++)
#pragma unroll
                for (int j = 0; j < 4; j++) acc[mt][nt][j] = 0.f;

#pragma unroll 2
        for (int chunk = 0; chunk < 36; chunk++) {
            const int tap = chunk >> 2;
            const int kc  = chunk & 3;
            const int ky  = tap / 3;
            const int kx  = tap - 3 * ky;
            const int ci0 = kc * 16;

            uint32_t ah[2][4], al[2][4];
#pragma unroll
            for (int mt = 0; mt < 2; mt++) {
                int row = (2 * wp + mt + ky) * 18 + pxoff + kx;
                uint32_t ad = sb + row * PROWB + (ci0 + cipart) * 2;
                ldsm_x4(ah[mt], ad);
                ldsm_x4(al[mt], ad + PATCH_BYTES);
            }
            const uint4* f = frag + ((size_t)chunk * NTOT + pass * NT) * 32 + lane;
#pragma unroll
            for (int nt = 0; nt < NT; nt++) {
                uint4 w4 = __ldg(f + nt * 32);
                uint32_t bh[2] = {w4.x, w4.y};
                uint32_t bl[2] = {w4.z, w4.w};
#pragma unroll
                for (int mt = 0; mt < 2; mt++) {
                    mma16816(acc[mt][nt], ah[mt], bh);
                    mma16816(acc[mt][nt], ah[mt], bl);
                    mma16816(acc[mt][nt], al[mt], bh);
                }
            }
        }

        // epilogue for this pass
#pragma unroll
        for (int mt = 0; mt < 2; mt++) {
            int gy = hy0 + 2 * wp + mt;
            int gx = wx0 + qr;
#pragma unroll
            for (int nt = 0; nt < NT; nt++) {
                int o = co0 + nt * 8 + qc * 2;
                float b0 = bias[o], b1 = bias[o + 1];
                size_t i00 = ((size_t)(b * Cout + o) * HH + gy) * WW + gx;
                size_t i01 = i00 + HW;
                float v0 = acc[mt][nt][0] + b0;
                float v1 = acc[mt][nt][1] + b1;
                float v2 = acc[mt][nt][2] + b0;
                float v3 = acc[mt][nt][3] + b1;
                if (RESID) {
                    v0 += resid[i00];     v1 += resid[i01];
                    v2 += resid[i00 + 8]; v3 += resid[i01 + 8];
                }
                out[i00] = v0;
                out[i01] = v1;
                out[i00 + 8] = v2;
                out[i01 + 8] = v3;
            }
        }
    }
}

// =================================================================
// Deformable sampling + grouped einsum via mma.sync, fused bias+leaky.
// R9-proven: warp-private A staging (__syncwarp), uint2 hi/lo B frags.
// =================================================================
__global__ __launch_bounds__(128) void deform_mma_k(
    const float* __restrict__ x, const float* __restrict__ om,
    const uint2* __restrict__ fragH, const uint2* __restrict__ fragL,
    const float* __restrict__ bdcn, float* __restrict__ fea)
{
    __shared__ uint32_t sAh[128 * 9];
    __shared__ uint32_t sAl[128 * 9];

    const int tid  = threadIdx.x;
    const int wp   = tid >> 5;
    const int lane = tid & 31;
    const int qr   = lane >> 2;
    const int qc   = lane & 3;
    const int px   = tid & 15;
    const int py   = tid >> 4;

    const int wx0 = blockIdx.x * 16;
    const int hy0 = blockIdx.y * 8;
    const int b   = blockIdx.z;
    const int w0  = wx0 + px;
    const int h0  = hy0 + py;
    const int pidx = h0 * WW + w0;

    const float* omb = om + (size_t)b * 216 * HW;
    const float* xb  = x  + (size_t)b * 64  * HW;

    float acc[2][8][4];
#pragma unroll
    for (int mt = 0; mt < 2; mt++)
#pragma unroll
        for (int nt = 0; nt < 8; nt++)
#pragma unroll
            for (int j = 0; j < 4; j++) acc[mt][nt][j] = 0.f;

    int g = 0, kt = 0;

#pragma unroll 1
    for (int chunk = 0; chunk < 36; chunk++) {
#pragma unroll
        for (int half = 0; half < 2; half++) {
            const int gk = chunk * 2 + half;
            float oy = __ldg(&omb[(size_t)gk * HW + pidx]);
            float ox = __ldg(&omb[(size_t)(72 + gk) * HW + pidx]);
            float ml = __ldg(&omb[(size_t)(144 + gk) * HW + pidx]);
            float m  = 1.f / (1.f + __expf(-ml));

            float pyf = (float)(h0 + kt / 3 - 1) + oy;
            float pxf = (float)(w0 + kt % 3 - 1) + ox;
            float y0f = floorf(pyf), x0f = floorf(pxf);
            float fy = pyf - y0f, fx = pxf - x0f;
            int y0 = (int)y0f, x0 = (int)x0f;
            int y1 = y0 + 1,  x1 = x0 + 1;

            float vy0 = (y0 >= 0 && y0 < HH) ? 1.f : 0.f;
            float vy1 = (y1 >= 0 && y1 < HH) ? 1.f : 0.f;
            float vx0 = (x0 >= 0 && x0 < WW) ? 1.f : 0.f;
            float vx1 = (x1 >= 0 && x1 < WW) ? 1.f : 0.f;
            int yc0 = min(max(y0, 0), HH - 1);
            int yc1 = min(max(y1, 0), HH - 1);
            int xc0 = min(max(x0, 0), WW - 1);
            int xc1 = min(max(x1, 0), WW - 1);

            float w00 = (1.f - fy) * (1.f - fx) * vy0 * vx0 * m;
            float w01 = (1.f - fy) * fx        * vy0 * vx1 * m;
            float w10 = fy        * (1.f - fx) * vy1 * vx0 * m;
            float w11 = fy        * fx         * vy1 * vx1 * m;

            int i00 = yc0 * WW + xc0;
            int i01 = yc0 * WW + xc1;
            int i10 = yc1 * WW + xc0;
            int i11 = yc1 * WW + xc1;

            const float* xg = xb + g * 8 * HW;
#pragma unroll
            for (int c = 0; c < 8; c += 2) {
                const float* xc0p = xg + c * HW;
                const float* xc1p = xg + (c + 1) * HW;
                float v0 = w00 * __ldg(xc0p + i00) + w01 * __ldg(xc0p + i01)
                         + w10 * __ldg(xc0p + i10) + w11 * __ldg(xc0p + i11);
                float v1 = w00 * __ldg(xc1p + i00) + w01 * __ldg(xc1p + i01)
                         + w10 * __ldg(xc1p + i10) + w11 * __ldg(xc1p + i11);
                float h0v = __bfloat162float(__float2bfloat16(v0));
                float h1v = __bfloat162float(__float2bfloat16(v1));
                int widx = tid * 9 + half * 4 + (c >> 1);
                sAh[widx] = pack_bf16x2(h0v, h1v);
                sAl[widx] = pack_bf16x2(v0 - h0v, v1 - h1v);
            }
            if (++kt == 9) { kt = 0; g++; }
        }
        __syncwarp();

        uint32_t ah[2][4], al[2][4];
#pragma unroll
        for (int mt = 0; mt < 2; mt++) {
            int y = 2 * wp + mt;
            int i0 = (y * 16 + qr) * 9 + qc;
            int i1 = (y * 16 + qr + 8) * 9 + qc;
            ah[mt][0] = sAh[i0];
            ah[mt][1] = sAh[i1];
            ah[mt][2] = sAh[i0 + 4];
            ah[mt][3] = sAh[i1 + 4];
            al[mt][0] = sAl[i0];
            al[mt][1] = sAl[i1];
            al[mt][2] = sAl[i0 + 4];
            al[mt][3] = sAl[i1 + 4];
        }
        const uint2* fh = fragH + (size_t)chunk * 256 + lane;
        const uint2* fl = fragL + (size_t)chunk * 256 + lane;
#pragma unroll
        for (int nt = 0; nt < 8; nt++) {
            uint2 bhv2 = __ldg(fh + nt * 32);
            uint2 blv2 = __ldg(fl + nt * 32);
            uint32_t bh[2] = {bhv2.x, bhv2.y};
            uint32_t bl[2] = {blv2.x, blv2.y};
#pragma unroll
            for (int mt = 0; mt < 2; mt++) {
                mma16816(acc[mt][nt], ah[mt], bh);
                mma16816(acc[mt][nt], ah[mt], bl);
                mma16816(acc[mt][nt], al[mt], bh);
            }
        }
        __syncwarp();
    }

#pragma unroll
    for (int mt = 0; mt < 2; mt++) {
        int gy = hy0 + 2 * wp + mt;
        int gx = wx0 + qr;
        int pi = gy * WW + gx;
#pragma unroll
        for (int nt = 0; nt < 8; nt++) {
            int o = nt * 8 + qc * 2;
            float b0 = bdcn[o], b1 = bdcn[o + 1];
            float v0 = acc[mt][nt][0] + b0;
            float v1 = acc[mt][nt][1] + b1;
            float v2 = acc[mt][nt][2] + b0;
            float v3 = acc[mt][nt][3] + b1;
            v0 = (v0 >= 0.f) ? v0 : 0.2f * v0;
            v1 = (v1 >= 0.f) ? v1 : 0.2f * v1;
            v2 = (v2 >= 0.f) ? v2 : 0.2f * v2;
            v3 = (v3 >= 0.f) ? v3 : 0.2f * v3;
            size_t o0i = (size_t)(b * 64 + o) * HW + pi;
            size_t o1i = o0i + HW;
            fea[o0i]     = v0;
            fea[o1i]     = v1;
            fea[o0i + 8] = v2;
            fea[o1i + 8] = v3;
        }
    }
}

// =================================================================
// Launch
// =================================================================
extern "C" void kernel_launch(void* const* d_in, const int* in_sizes, int n_in,
                              void* d_out, int out_size)
{
    const float* x       = (const float*)d_in[0];
    const float* offset  = (const float*)d_in[1];
    const float* w_off   = (const float*)d_in[2];
    const float* b_off   = (const float*)d_in[3];
    const float* w_dcn   = (const float*)d_in[4];
    const float* b_dcn   = (const float*)d_in[5];
    const float* w_conv1 = (const float*)d_in[6];
    const float* b_conv1 = (const float*)d_in[7];
    float* out = (float*)d_out;

    void *p_om, *p_fea, *p_A, *p_B, *p_DH, *p_DL;
    cudaGetSymbolAddress(&p_om, g_om);
    cudaGetSymbolAddress(&p_fea, g_fea);
    cudaGetSymbolAddress(&p_A, g_fA);
    cudaGetSymbolAddress(&p_B, g_fB);
    cudaGetSymbolAddress(&p_DH, g_fDH);
    cudaGetSymbolAddress(&p_DL, g_fDL);
    float* om  = (float*)p_om;
    float* fea = (float*)p_fea;

    const int SMEM_C = 2 * PATCH_BYTES;   // 51840

    cudaFuncSetAttribute((const void*)conv_mma<9, 3, false>,
                         cudaFuncAttributeMaxDynamicSharedMemorySize, SMEM_C);
    cudaFuncSetAttribute((const void*)conv_mma<8, 1, true>,
                         cudaFuncAttributeMaxDynamicSharedMemorySize, SMEM_C);

    // 0) weight prep (fragment packing)
    prep_conv_frag<<<(36 * 27 * 32 + 255) / 256, 256>>>(w_off, (uint4*)p_A, 216);
    prep_conv_frag<<<(36 * 8 * 32 + 255) / 256, 256>>>(w_conv1, (uint4*)p_B, 64);
    prep_wd_frag<<<(36 * 8 * 32 + 255) / 256, 256>>>(w_dcn, (uint2*)p_DH, (uint2*)p_DL);

    // 1) offset conv: 64 -> 216, 3 in-block N-passes, patch staged once
    conv_mma<9, 3, false><<<dim3(6, 12, BB), 128, SMEM_C>>>(
        offset, (const uint4*)p_A, b_off, nullptr, om, 216);

    // 2) deformable sampling + grouped einsum + bias + leaky
    deform_mma_k<<<dim3(6, 12, BB), 128>>>(
        x, om, (const uint2*)p_DH, (const uint2*)p_DL, b_dcn, fea);

    // 3) conv1: 64 -> 64 + residual
    conv_mma<8, 1, true><<<dim3(6, 12, BB), 128, SMEM_C>>>(
        fea, (const uint4*)p_B, b_conv1, x, out, 64);
}

// round 17
// speedup vs baseline: 1.3322x; 1.0035x over previous
#include <cuda_runtime.h>
#include <cuda_bf16.h>
#include <cstdint>
#include <math.h>

// Problem constants
#define HH 96
#define WW 96
#define BB 4
#define CIN 64
#define HW (HH*WW)

// ---------------- scratch (no allocations allowed) ----------------
__device__ float g_om[(size_t)BB * 216 * HW];        // offset-conv output
__device__ float g_fea[(size_t)BB * 64 * HW];        // activated dcn output
__device__ uint4 g_fA[36 * 27 * 32];                 // offset-conv B frags (hi0,hi1,lo0,lo1)
__device__ uint4 g_fB[36 * 8 * 32];                  // conv1 B frags
__device__ uint2 g_fDH[36 * 8 * 32];                 // w_dcn B frags hi
__device__ uint2 g_fDL[36 * 8 * 32];                 // lo

// ---------------- warp MMA: m16n8k16 row.col f32.bf16.bf16.f32 ----------------
__device__ __forceinline__ void mma16816(float* d, const uint32_t* a, const uint32_t* b) {
    asm volatile(
        "mma.sync.aligned.m16n8k16.row.col.f32.bf16.bf16.f32 "
        "{%0,%1,%2,%3}, {%4,%5,%6,%7}, {%8,%9}, {%0,%1,%2,%3};"
        : "+f"(d[0]), "+f"(d[1]), "+f"(d[2]), "+f"(d[3])
        : "r"(a[0]), "r"(a[1]), "r"(a[2]), "r"(a[3]), "r"(b[0]), "r"(b[1]));
}

__device__ __forceinline__ void ldsm_x4(uint32_t* r, uint32_t addr) {
    asm volatile("ldmatrix.sync.aligned.m8n8.x4.shared.b16 {%0,%1,%2,%3}, [%4];"
                 : "=r"(r[0]), "=r"(r[1]), "=r"(r[2]), "=r"(r[3]) : "r"(addr));
}

__device__ __forceinline__ uint32_t smem_u32(const void* p) {
    uint32_t a;
    asm("{ .reg .u64 t; cvta.to.shared.u64 t, %1; cvt.u32.u64 %0, t; }" : "=r"(a) : "l"(p));
    return a;
}

__device__ __forceinline__ uint32_t pack_bf16x2(float a, float b) {
    __nv_bfloat16 ha = __float2bfloat16(a);
    __nv_bfloat16 hb = __float2bfloat16(b);
    return ((uint32_t)__bfloat16_as_ushort(hb) << 16) | (uint32_t)__bfloat16_as_ushort(ha);
}

// =================================================================
// Conv weight prep: fp32 w[Cout][64ci][9tap] -> MMA B fragments packed
// (hi0,hi1,lo0,lo1) per [chunk][ntG][lane]. chunk = tap*4 + kc.
// =================================================================
__global__ void prep_conv_frag(const float* __restrict__ w,
                               uint4* __restrict__ f, int Cout)
{
    int NTOT = Cout >> 3;
    int total = 36 * NTOT * 32;
    int i = blockIdx.x * 256 + threadIdx.x;
    if (i >= total) return;
    int lane = i & 31;
    int ntG  = (i >> 5) % NTOT;
    int chunk = i / (NTOT * 32);
    int tap = chunk >> 2;
    int ci0 = (chunk & 3) * 16;
    int qr = lane >> 2, qc = lane & 3;
    int o = ntG * 8 + qr;
    uint32_t wh[2], wl[2];
#pragma unroll
    for (int half = 0; half < 2; half++) {
        int ci = ci0 + half * 8 + qc * 2;
        float wa = w[(size_t)(o * 64 + ci) * 9 + tap];
        float wb = w[(size_t)(o * 64 + ci + 1) * 9 + tap];
        float ha = __bfloat162float(__float2bfloat16(wa));
        float hb = __bfloat162float(__float2bfloat16(wb));
        wh[half] = pack_bf16x2(ha, hb);
        wl[half] = pack_bf16x2(wa - ha, wb - hb);
    }
    f[i] = make_uint4(wh[0], wh[1], wl[0], wl[1]);
}

// =================================================================
// DCN einsum weight prep: w_dcn[64o][64gc][9k] -> per-chunk B frags
// (uint2 hi / uint2 lo, separate arrays — R9-proven layout).
// =================================================================
__global__ void prep_wd_frag(const float* __restrict__ wdcn,
                             uint2* __restrict__ fh, uint2* __restrict__ fl)
{
    int i = blockIdx.x * 256 + threadIdx.x;
    if (i >= 36 * 8 * 32) return;
    int lane = i & 31;
    int nt = (i >> 5) & 7;
    int chunk = i >> 8;
    int qr = lane >> 2, qc = lane & 3;
    int o = nt * 8 + qr;
    uint32_t wh[2], wl[2];
#pragma unroll
    for (int half = 0; half < 2; half++) {
        int gk = chunk * 2 + half;
        int g = gk / 9, kt = gk - 9 * g;
        int c = qc * 2;
        float wa = wdcn[(size_t)(o * 64 + g * 8 + c) * 9 + kt];
        float wb = wdcn[(size_t)(o * 64 + g * 8 + c + 1) * 9 + kt];
        float ha = __bfloat162float(__float2bfloat16(wa));
        float hb = __bfloat162float(__float2bfloat16(wb));
        wh[half] = pack_bf16x2(ha, hb);
        wl[half] = pack_bf16x2(wa - ha, wb - hb);
    }
    fh[i] = make_uint2(wh[0], wh[1]);
    fl[i] = make_uint2(wl[0], wl[1]);
}

// =================================================================
// 3x3 conv (pad 1, Cin=64) via mma.sync — ldmatrix A + uint4-packed B.
// Block: 256 threads / 8 warps. M=128 px (8x16): warp pair (wp>>1) owns
// pixel rows 2(wp>>1), 2(wp>>1)+1 (two m16 A-tiles); wp&1 selects the
// N-half, so per-warp B-LDG and HMMA halve together (ratio preserved)
// while warps/SM double. N covered by NPASS in-block passes (patch
// staged ONCE). Flattened 36-chunk loop, unroll 2.
// =================================================================
constexpr int PS = 72;                       // ci stride (elems)
constexpr int PROWB = PS * 2;                // 144 bytes per pixel-row
constexpr int PATCH_BYTES = 180 * PROWB;     // 25920

template<int NTB, int NPASS, bool RESID>
__global__ __launch_bounds__(256, 2) void conv_mma(
    const float* __restrict__ in,
    const uint4* __restrict__ frag,
    const float* __restrict__ bias, const float* __restrict__ resid,
    float* __restrict__ out, int Cout)
{
    extern __shared__ __align__(16) char smem[];
    __nv_bfloat16* phi = (__nv_bfloat16*)smem;
    __nv_bfloat16* plo = (__nv_bfloat16*)(smem + PATCH_BYTES);

    constexpr int NTMAX = (NTB + 1) / 2;     // 9->5, 8->4

    const int tid  = threadIdx.x;
    const int wp   = tid >> 5;               // 0..7
    const int lane = tid & 31;
    const int qr   = lane >> 2;
    const int qc   = lane & 3;
    const int mrow = wp >> 1;                // 0..3: pixel row pair
    const int ns   = wp & 1;                 // N-half
    const int ntbase = ns ? NTMAX : 0;
    const int ntcnt  = ns ? (NTB - NTMAX) : NTMAX;
    const int pxoff  = (lane & 7) + ((lane >> 3) & 1) * 8;
    const int cipart = (lane >> 4) * 8;

    const int wx0 = blockIdx.x * 16;
    const int hy0 = blockIdx.y * 8;
    const int b   = blockIdx.z;
    const int NTOT = Cout >> 3;

    const uint32_t sb = smem_u32(smem);

    const float* inb = in + (size_t)b * CIN * HW;
    for (int e = tid; e < 180 * 64; e += 256) {
        int x  = e % 18;
        int y  = (e / 18) % 10;
        int ci = e / 180;
        int gy = hy0 + y - 1;
        int gx = wx0 + x - 1;
        float v = 0.f;
        if ((unsigned)gy < HH && (unsigned)gx < WW)
            v = inb[ci * HW + gy * WW + gx];
        __nv_bfloat16 h = __float2bfloat16(v);
        __nv_bfloat16 l = __float2bfloat16(v - __bfloat162float(h));
        int d = (y * 18 + x) * PS + ci;
        phi[d] = h;
        plo[d] = l;
    }
    __syncthreads();

#pragma unroll 1
    for (int pass = 0; pass < NPASS; pass++) {
        const int co0 = pass * NTB * 8;

        float acc[2][NTMAX][4];
#pragma unroll
        for (int mt = 0; mt < 2; mt++)
#pragma unroll
            for (int nt = 0; nt < NTMAX; nt++)
#pragma unroll
                for (int j = 0; j < 4; j++) acc[mt][nt][j] = 0.f;

#pragma unroll 2
        for (int chunk = 0; chunk < 36; chunk++) {
            const int tap = chunk >> 2;
            const int kc  = chunk & 3;
            const int ky  = tap / 3;
            const int kx  = tap - 3 * ky;
            const int ci0 = kc * 16;

            uint32_t ah[2][4], al[2][4];
#pragma unroll
            for (int mt = 0; mt < 2; mt++) {
                int row = (2 * mrow + mt + ky) * 18 + pxoff + kx;
                uint32_t ad = sb + row * PROWB + (ci0 + cipart) * 2;
                ldsm_x4(ah[mt], ad);
                ldsm_x4(al[mt], ad + PATCH_BYTES);
            }
            const uint4* f = frag + ((size_t)chunk * NTOT + pass * NTB + ntbase) * 32 + lane;
#pragma unroll
            for (int nt = 0; nt < NTMAX; nt++) {
                if (nt < ntcnt) {
                    uint4 w4 = __ldg(f + nt * 32);
                    uint32_t bh[2] = {w4.x, w4.y};
                    uint32_t bl[2] = {w4.z, w4.w};
#pragma unroll
                    for (int mt = 0; mt < 2; mt++) {
                        mma16816(acc[mt][nt], ah[mt], bh);
                        mma16816(acc[mt][nt], ah[mt], bl);
                        mma16816(acc[mt][nt], al[mt], bh);
                    }
                }
            }
        }

        // epilogue for this pass
#pragma unroll
        for (int mt = 0; mt < 2; mt++) {
            int gy = hy0 + 2 * mrow + mt;
            int gx = wx0 + qr;
#pragma unroll
            for (int nt = 0; nt < NTMAX; nt++) {
                if (nt < ntcnt) {
                    int o = co0 + (ntbase + nt) * 8 + qc * 2;
                    float b0 = bias[o], b1 = bias[o + 1];
                    size_t i00 = ((size_t)(b * Cout + o) * HH + gy) * WW + gx;
                    size_t i01 = i00 + HW;
                    float v0 = acc[mt][nt][0] + b0;
                    float v1 = acc[mt][nt][1] + b1;
                    float v2 = acc[mt][nt][2] + b0;
                    float v3 = acc[mt][nt][3] + b1;
                    if (RESID) {
                        v0 += resid[i00];     v1 += resid[i01];
                        v2 += resid[i00 + 8]; v3 += resid[i01 + 8];
                    }
                    out[i00] = v0;
                    out[i01] = v1;
                    out[i00 + 8] = v2;
                    out[i01 + 8] = v3;
                }
            }
        }
    }
}

// =================================================================
// Deformable sampling + grouped einsum via mma.sync, fused bias+leaky.
// R9-proven: warp-private A staging (__syncwarp), uint2 hi/lo B frags.
// =================================================================
__global__ __launch_bounds__(128) void deform_mma_k(
    const float* __restrict__ x, const float* __restrict__ om,
    const uint2* __restrict__ fragH, const uint2* __restrict__ fragL,
    const float* __restrict__ bdcn, float* __restrict__ fea)
{
    __shared__ uint32_t sAh[128 * 9];
    __shared__ uint32_t sAl[128 * 9];

    const int tid  = threadIdx.x;
    const int wp   = tid >> 5;
    const int lane = tid & 31;
    const int qr   = lane >> 2;
    const int qc   = lane & 3;
    const int px   = tid & 15;
    const int py   = tid >> 4;

    const int wx0 = blockIdx.x * 16;
    const int hy0 = blockIdx.y * 8;
    const int b   = blockIdx.z;
    const int w0  = wx0 + px;
    const int h0  = hy0 + py;
    const int pidx = h0 * WW + w0;

    const float* omb = om + (size_t)b * 216 * HW;
    const float* xb  = x  + (size_t)b * 64  * HW;

    float acc[2][8][4];
#pragma unroll
    for (int mt = 0; mt < 2; mt++)
#pragma unroll
        for (int nt = 0; nt < 8; nt++)
#pragma unroll
            for (int j = 0; j < 4; j++) acc[mt][nt][j] = 0.f;

    int g = 0, kt = 0;

#pragma unroll 1
    for (int chunk = 0; chunk < 36; chunk++) {
#pragma unroll
        for (int half = 0; half < 2; half++) {
            const int gk = chunk * 2 + half;
            float oy = __ldg(&omb[(size_t)gk * HW + pidx]);
            float ox = __ldg(&omb[(size_t)(72 + gk) * HW + pidx]);
            float ml = __ldg(&omb[(size_t)(144 + gk) * HW + pidx]);
            float m  = 1.f / (1.f + __expf(-ml));

            float pyf = (float)(h0 + kt / 3 - 1) + oy;
            float pxf = (float)(w0 + kt % 3 - 1) + ox;
            float y0f = floorf(pyf), x0f = floorf(pxf);
            float fy = pyf - y0f, fx = pxf - x0f;
            int y0 = (int)y0f, x0 = (int)x0f;
            int y1 = y0 + 1,  x1 = x0 + 1;

            float vy0 = (y0 >= 0 && y0 < HH) ? 1.f : 0.f;
            float vy1 = (y1 >= 0 && y1 < HH) ? 1.f : 0.f;
            float vx0 = (x0 >= 0 && x0 < WW) ? 1.f : 0.f;
            float vx1 = (x1 >= 0 && x1 < WW) ? 1.f : 0.f;
            int yc0 = min(max(y0, 0), HH - 1);
            int yc1 = min(max(y1, 0), HH - 1);
            int xc0 = min(max(x0, 0), WW - 1);
            int xc1 = min(max(x1, 0), WW - 1);

            float w00 = (1.f - fy) * (1.f - fx) * vy0 * vx0 * m;
            float w01 = (1.f - fy) * fx        * vy0 * vx1 * m;
            float w10 = fy        * (1.f - fx) * vy1 * vx0 * m;
            float w11 = fy        * fx         * vy1 * vx1 * m;

            int i00 = yc0 * WW + xc0;
            int i01 = yc0 * WW + xc1;
            int i10 = yc1 * WW + xc0;
            int i11 = yc1 * WW + xc1;

            const float* xg = xb + g * 8 * HW;
#pragma unroll
            for (int c = 0; c < 8; c += 2) {
                const float* xc0p = xg + c * HW;
                const float* xc1p = xg + (c + 1) * HW;
                float v0 = w00 * __ldg(xc0p + i00) + w01 * __ldg(xc0p + i01)
                         + w10 * __ldg(xc0p + i10) + w11 * __ldg(xc0p + i11);
                float v1 = w00 * __ldg(xc1p + i00) + w01 * __ldg(xc1p + i01)
                         + w10 * __ldg(xc1p + i10) + w11 * __ldg(xc1p + i11);
                float h0v = __bfloat162float(__float2bfloat16(v0));
                float h1v = __bfloat162float(__float2bfloat16(v1));
                int widx = tid * 9 + half * 4 + (c >> 1);
                sAh[widx] = pack_bf16x2(h0v, h1v);
                sAl[widx] = pack_bf16x2(v0 - h0v, v1 - h1v);
            }
            if (++kt == 9) { kt = 0; g++; }
        }
        __syncwarp();

        uint32_t ah[2][4], al[2][4];
#pragma unroll
        for (int mt = 0; mt < 2; mt++) {
            int y = 2 * wp + mt;
            int i0 = (y * 16 + qr) * 9 + qc;
            int i1 = (y * 16 + qr + 8) * 9 + qc;
            ah[mt][0] = sAh[i0];
            ah[mt][1] = sAh[i1];
            ah[mt][2] = sAh[i0 + 4];
            ah[mt][3] = sAh[i1 + 4];
            al[mt][0] = sAl[i0];
            al[mt][1] = sAl[i1];
            al[mt][2] = sAl[i0 + 4];
            al[mt][3] = sAl[i1 + 4];
        }
        const uint2* fh = fragH + (size_t)chunk * 256 + lane;
        const uint2* fl = fragL + (size_t)chunk * 256 + lane;
#pragma unroll
        for (int nt = 0; nt < 8; nt++) {
            uint2 bhv2 = __ldg(fh + nt * 32);
            uint2 blv2 = __ldg(fl + nt * 32);
            uint32_t bh[2] = {bhv2.x, bhv2.y};
            uint32_t bl[2] = {blv2.x, blv2.y};
#pragma unroll
            for (int mt = 0; mt < 2; mt++) {
                mma16816(acc[mt][nt], ah[mt], bh);
                mma16816(acc[mt][nt], ah[mt], bl);
                mma16816(acc[mt][nt], al[mt], bh);
            }
        }
        __syncwarp();
    }

#pragma unroll
    for (int mt = 0; mt < 2; mt++) {
        int gy = hy0 + 2 * wp + mt;
        int gx = wx0 + qr;
        int pi = gy * WW + gx;
#pragma unroll
        for (int nt = 0; nt < 8; nt++) {
            int o = nt * 8 + qc * 2;
            float b0 = bdcn[o], b1 = bdcn[o + 1];
            float v0 = acc[mt][nt][0] + b0;
            float v1 = acc[mt][nt][1] + b1;
            float v2 = acc[mt][nt][2] + b0;
            float v3 = acc[mt][nt][3] + b1;
            v0 = (v0 >= 0.f) ? v0 : 0.2f * v0;
            v1 = (v1 >= 0.f) ? v1 : 0.2f * v1;
            v2 = (v2 >= 0.f) ? v2 : 0.2f * v2;
            v3 = (v3 >= 0.f) ? v3 : 0.2f * v3;
            size_t o0i = (size_t)(b * 64 + o) * HW + pi;
            size_t o1i = o0i + HW;
            fea[o0i]     = v0;
            fea[o1i]     = v1;
            fea[o0i + 8] = v2;
            fea[o1i + 8] = v3;
        }
    }
}

// =================================================================
// Launch
// =================================================================
extern "C" void kernel_launch(void* const* d_in, const int* in_sizes, int n_in,
                              void* d_out, int out_size)
{
    const float* x       = (const float*)d_in[0];
    const float* offset  = (const float*)d_in[1];
    const float* w_off   = (const float*)d_in[2];
    const float* b_off   = (const float*)d_in[3];
    const float* w_dcn   = (const float*)d_in[4];
    const float* b_dcn   = (const float*)d_in[5];
    const float* w_conv1 = (const float*)d_in[6];
    const float* b_conv1 = (const float*)d_in[7];
    float* out = (float*)d_out;

    void *p_om, *p_fea, *p_A, *p_B, *p_DH, *p_DL;
    cudaGetSymbolAddress(&p_om, g_om);
    cudaGetSymbolAddress(&p_fea, g_fea);
    cudaGetSymbolAddress(&p_A, g_fA);
    cudaGetSymbolAddress(&p_B, g_fB);
    cudaGetSymbolAddress(&p_DH, g_fDH);
    cudaGetSymbolAddress(&p_DL, g_fDL);
    float* om  = (float*)p_om;
    float* fea = (float*)p_fea;

    const int SMEM_C = 2 * PATCH_BYTES;   // 51840

    cudaFuncSetAttribute((const void*)conv_mma<9, 3, false>,
                         cudaFuncAttributeMaxDynamicSharedMemorySize, SMEM_C);
    cudaFuncSetAttribute((const void*)conv_mma<8, 1, true>,
                         cudaFuncAttributeMaxDynamicSharedMemorySize, SMEM_C);

    // 0) weight prep (fragment packing)
    prep_conv_frag<<<(36 * 27 * 32 + 255) / 256, 256>>>(w_off, (uint4*)p_A, 216);
    prep_conv_frag<<<(36 * 8 * 32 + 255) / 256, 256>>>(w_conv1, (uint4*)p_B, 64);
    prep_wd_frag<<<(36 * 8 * 32 + 255) / 256, 256>>>(w_dcn, (uint2*)p_DH, (uint2*)p_DL);

    // 1) offset conv: 64 -> 216, 3 in-block N-passes, warp-split N halves
    conv_mma<9, 3, false><<<dim3(6, 12, BB), 256, SMEM_C>>>(
        offset, (const uint4*)p_A, b_off, nullptr, om, 216);

    // 2) deformable sampling + grouped einsum + bias + leaky
    deform_mma_k<<<dim3(6, 12, BB), 128>>>(
        x, om, (const uint2*)p_DH, (const uint2*)p_DL, b_dcn, fea);

    // 3) conv1: 64 -> 64 + residual
    conv_mma<8, 1, true><<<dim3(6, 12, BB), 256, SMEM_C>>>(
        fea, (const uint4*)p_B, b_conv1, x, out, 64);
}